// round 4
// baseline (speedup 1.0000x reference)
#include <cuda_runtime.h>

#define T_STEPS 2048
#define BATCH   2048
#define HID     32
#define DF      8
#define DS      24
#define WARPS_PER_CTA 4

// ---------- f32x2 packed helpers (sm_100+) ----------
__device__ __forceinline__ unsigned long long f2_fma(unsigned long long a,
                                                     unsigned long long b,
                                                     unsigned long long c) {
    unsigned long long d;
    asm("fma.rn.f32x2 %0, %1, %2, %3;" : "=l"(d) : "l"(a), "l"(b), "l"(c));
    return d;
}
__device__ __forceinline__ unsigned long long f2_add(unsigned long long a,
                                                     unsigned long long b) {
    unsigned long long d;
    asm("add.rn.f32x2 %0, %1, %2;" : "=l"(d) : "l"(a), "l"(b));
    return d;
}
__device__ __forceinline__ unsigned long long f2_pack(float lo, float hi) {
    unsigned long long d;
    asm("mov.b64 %0, {%1, %2};" : "=l"(d) : "f"(lo), "f"(hi));
    return d;
}
__device__ __forceinline__ void f2_unpack(unsigned long long v, float &lo, float &hi) {
    asm("mov.b64 {%0, %1}, %2;" : "=f"(lo), "=f"(hi) : "l"(v));
}

// tanh(x) = sign(x) * (1 - e) / (1 + e), e = exp(-2|x|). ~1e-6 abs error.
__device__ __forceinline__ float fast_tanh(float x) {
    float ax = fabsf(x);
    float e  = __expf(-2.0f * ax);
    float r  = __fdividef(1.0f - e, 1.0f + e);
    return __int_as_float((__float_as_int(x) & 0x80000000) | __float_as_int(r));
}

__device__ __forceinline__ unsigned long long lds2(const float* p) {
    return *reinterpret_cast<const unsigned long long*>(p);
}
__device__ __forceinline__ void sts2(float* p, unsigned long long v) {
    *reinterpret_cast<unsigned long long*>(p) = v;
}

__global__ __launch_bounds__(WARPS_PER_CTA * 32)
void chive_kernel(const float* __restrict__ frnn, const float* __restrict__ phrnn,
                  const float* __restrict__ syl,
                  const float* __restrict__ Wx_f, const float* __restrict__ Wh_f,
                  const float* __restrict__ b_f,
                  const float* __restrict__ Wx_p, const float* __restrict__ Wh_p,
                  const float* __restrict__ b_p,
                  const float* __restrict__ Wx_s, const float* __restrict__ Wh_s,
                  const float* __restrict__ b_s,
                  const int* __restrict__ fclk, const int* __restrict__ pclk,
                  const int* __restrict__ sfreq,
                  float* __restrict__ out)
{
    // Interleaved weight stages (pairs for f32x2 ops)
    __shared__ __align__(16) float sWx[DF * HID * 2];    // (Wx_f, Wx_p) interleaved
    __shared__ __align__(16) float sWh[HID * HID * 2];   // (Wh_f, Wh_p) interleaved
    __shared__ __align__(16) float sBfp[HID * 2];        // (b_f, b_p)
    __shared__ __align__(16) float sWxsD[HID * HID * 2]; // Wx_s duplicated (w,w)
    __shared__ __align__(16) float sWhsD[HID * HID * 2]; // Wh_s duplicated (w,w)
    __shared__ __align__(16) float sWs2[HID * HID * 2];  // (Wx_s, Wh_s) interleaved
    __shared__ __align__(16) float sBs[HID];
    __shared__ unsigned char sFlag[T_STEPS];
    // per-warp state (broadcast copies)
    __shared__ __align__(16) float sHfp[WARPS_PER_CTA][HID * 2];
    __shared__ __align__(16) float sHs01[WARPS_PER_CTA][HID * 2];
    __shared__ __align__(16) float sXfp[WARPS_PER_CTA][DF * 2];
    __shared__ __align__(16) float sR2[WARPS_PER_CTA][HID * 2];

    const int tid = threadIdx.x;
    const int nt  = blockDim.x;

    // ---- prologue: stage weights + precompute per-step update flags ----
    for (int i = tid; i < DF * HID; i += nt) {
        sWx[2 * i]     = Wx_f[i];
        sWx[2 * i + 1] = Wx_p[i];
    }
    for (int i = tid; i < HID * HID; i += nt) {
        sWh[2 * i]     = Wh_f[i];
        sWh[2 * i + 1] = Wh_p[i];
        float wx = Wx_s[i], wh = Wh_s[i];
        sWxsD[2 * i] = wx;  sWxsD[2 * i + 1] = wx;
        sWhsD[2 * i] = wh;  sWhsD[2 * i + 1] = wh;
        sWs2[2 * i]  = wx;  sWs2[2 * i + 1]  = wh;
    }
    for (int i = tid; i < HID; i += nt) {
        sBfp[2 * i]     = b_f[i];
        sBfp[2 * i + 1] = b_p[i];
        sBs[i]          = b_s[i];
    }
    for (int t = tid; t < T_STEPS; t += nt) {
        unsigned f = 0u;
        if ((t % (fclk[t] + 1)) == 0) f |= 1u;
        if ((t % (pclk[t] + 1)) == 0) f |= 2u;
        if (sfreq[t] == 1)            f |= 4u;
        sFlag[t] = (unsigned char)f;
    }

    const int w    = tid >> 5;
    const int lane = tid & 31;
    const int b    = blockIdx.x * WARPS_PER_CTA + w;

    float* Hfp  = sHfp[w];
    float* Hs01 = sHs01[w];
    float* Xfp  = sXfp[w];
    float* R2   = sR2[w];

    // registers: own-lane state
    float hf = 0.f, hp = 0.f, hs0 = 0.f, hs1 = 0.f, hs2 = 0.f;
    sts2(&Hfp[2 * lane], 0ull);
    sts2(&Hs01[2 * lane], 0ull);
    __syncthreads();

    // prefetch step-0 inputs (xs pre-padded: lanes >= DS carry 0)
    float xf_c = 0.f, xp_c = 0.f, xs_c = 0.f;
    if (lane < DF) {
        xf_c = frnn[b * DF + lane];
        xp_c = phrnn[b * DF + lane];
    }
    if (lane < DS) xs_c = syl[b * DS + lane];

    for (int t = 0; t < T_STEPS; t++) {
        // prefetch next-step inputs (hidden under this step's compute)
        float xf_n = 0.f, xp_n = 0.f, xs_n = 0.f;
        if (t + 1 < T_STEPS) {
            int base = (t + 1) * BATCH + b;
            if (lane < DF) {
                xf_n = frnn[base * DF + lane];
                xp_n = phrnn[base * DF + lane];
            }
            if (lane < DS) xs_n = syl[base * DS + lane];
        }

        unsigned fl = sFlag[t];

        // ---------------- phase A: f & p cells (packed f32x2) ----------------
        if (fl & 3u) {
            if (lane < DF) sts2(&Xfp[2 * lane], f2_pack(xf_c, xp_c));
            __syncwarp();

            unsigned long long accA = lds2(&sBfp[2 * lane]);
            unsigned long long accB = 0ull;
            #pragma unroll
            for (int j = 0; j < DF; j++) {
                unsigned long long xj = lds2(&Xfp[2 * j]);
                unsigned long long wj = lds2(&sWx[(j * HID + lane) * 2]);
                if (j & 1) accB = f2_fma(xj, wj, accB);
                else       accA = f2_fma(xj, wj, accA);
            }
            #pragma unroll
            for (int j = 0; j < HID; j++) {
                unsigned long long hj = lds2(&Hfp[2 * j]);
                unsigned long long wj = lds2(&sWh[(j * HID + lane) * 2]);
                if (j & 1) accB = f2_fma(hj, wj, accB);
                else       accA = f2_fma(hj, wj, accA);
            }
            unsigned long long acc = f2_add(accA, accB);
            float af, ap;
            f2_unpack(acc, af, ap);
            if (fl & 1u) hf = fast_tanh(af);
            if (fl & 2u) hp = fast_tanh(ap);
            __syncwarp();  // all lanes done reading old Hfp
            sts2(&Hfp[2 * lane], f2_pack(hf, hp));
        }

        // ---------------- phase B: syl cell (3 rows) ----------------
        if (fl & 4u) {
            // row2 operand pair: (x_s[j] padded, h_s2[j])
            sts2(&R2[2 * lane], f2_pack(xs_c, hs2));
            __syncwarp();  // also publishes phase-A Hfp store

            float bs = sBs[lane];
            unsigned long long accX  = f2_pack(bs, bs);   // rows (0,1): x-stack part
            unsigned long long accH  = 0ull;              // rows (0,1): Wh part
            unsigned long long acc2a = f2_pack(bs, 0.f);  // row2: (x-part, h-part)
            unsigned long long acc2b = 0ull;
            #pragma unroll
            for (int j = 0; j < HID; j++) {
                unsigned long long hfpj = lds2(&Hfp[2 * j]);
                unsigned long long wx   = lds2(&sWxsD[(j * HID + lane) * 2]);
                accX = f2_fma(hfpj, wx, accX);
                unsigned long long h01j = lds2(&Hs01[2 * j]);
                unsigned long long wh   = lds2(&sWhsD[(j * HID + lane) * 2]);
                accH = f2_fma(h01j, wh, accH);
                unsigned long long r2j  = lds2(&R2[2 * j]);
                unsigned long long w2   = lds2(&sWs2[(j * HID + lane) * 2]);
                if (j & 1) acc2b = f2_fma(r2j, w2, acc2b);
                else       acc2a = f2_fma(r2j, w2, acc2a);
            }
            unsigned long long acc01 = f2_add(accX, accH);
            float a0, a1;
            f2_unpack(acc01, a0, a1);
            unsigned long long acc2 = f2_add(acc2a, acc2b);
            float xpart, hpart;
            f2_unpack(acc2, xpart, hpart);
            hs0 = fast_tanh(a0);
            hs1 = fast_tanh(a1);
            hs2 = fast_tanh(xpart + hpart);
            __syncwarp();  // all lanes done reading old Hs01
            sts2(&Hs01[2 * lane], f2_pack(hs0, hs1));
        }

        xf_c = xf_n; xp_c = xp_n; xs_c = xs_n;
    }

    // output h_s: [3, B, H]
    out[(0 * BATCH + b) * HID + lane] = hs0;
    out[(1 * BATCH + b) * HID + lane] = hs1;
    out[(2 * BATCH + b) * HID + lane] = hs2;
}

extern "C" void kernel_launch(void* const* d_in, const int* in_sizes, int n_in,
                              void* d_out, int out_size) {
    const float* frnn  = (const float*)d_in[0];
    const float* phrnn = (const float*)d_in[1];
    const float* syl   = (const float*)d_in[2];
    const float* Wx_f  = (const float*)d_in[3];
    const float* Wh_f  = (const float*)d_in[4];
    const float* b_f   = (const float*)d_in[5];
    const float* Wx_p  = (const float*)d_in[6];
    const float* Wh_p  = (const float*)d_in[7];
    const float* b_p   = (const float*)d_in[8];
    const float* Wx_s  = (const float*)d_in[9];
    const float* Wh_s  = (const float*)d_in[10];
    const float* b_s   = (const float*)d_in[11];
    const int*   fclk  = (const int*)d_in[12];
    const int*   pclk  = (const int*)d_in[13];
    const int*   sfreq = (const int*)d_in[14];
    float* out = (float*)d_out;

    dim3 grid(BATCH / WARPS_PER_CTA);
    dim3 block(WARPS_PER_CTA * 32);
    chive_kernel<<<grid, block>>>(frnn, phrnn, syl,
                                  Wx_f, Wh_f, b_f,
                                  Wx_p, Wh_p, b_p,
                                  Wx_s, Wh_s, b_s,
                                  fclk, pclk, sfreq, out);
}

// round 5
// speedup vs baseline: 2.0226x; 2.0226x over previous
#include <cuda_runtime.h>

#define T_STEPS 2048
#define BATCH   2048
#define HID     32
#define DF      8
#define DS      24
#define WARPS_PER_CTA  2
#define ELEMS_PER_WARP 2

typedef unsigned long long ull;

// ---------- f32x2 packed helpers (sm_100+) ----------
__device__ __forceinline__ ull f2_fma(ull a, ull b, ull c) {
    ull d;
    asm("fma.rn.f32x2 %0, %1, %2, %3;" : "=l"(d) : "l"(a), "l"(b), "l"(c));
    return d;
}
__device__ __forceinline__ ull f2_add(ull a, ull b) {
    ull d;
    asm("add.rn.f32x2 %0, %1, %2;" : "=l"(d) : "l"(a), "l"(b));
    return d;
}
__device__ __forceinline__ ull f2_pack(float lo, float hi) {
    ull d;
    asm("mov.b64 %0, {%1, %2};" : "=l"(d) : "f"(lo), "f"(hi));
    return d;
}
__device__ __forceinline__ void f2_unpack(ull v, float &lo, float &hi) {
    asm("mov.b64 {%0, %1}, %2;" : "=f"(lo), "=f"(hi) : "l"(v));
}

// tanh(x) = sign(x) * (1 - e) / (1 + e), e = exp(-2|x|). ~1e-6 abs error.
__device__ __forceinline__ float fast_tanh(float x) {
    float ax = fabsf(x);
    float e  = __expf(-2.0f * ax);
    float r  = __fdividef(1.0f - e, 1.0f + e);
    return __int_as_float((__float_as_int(x) & 0x80000000) | __float_as_int(r));
}

__device__ __forceinline__ ull lds2(const float* p) {
    return *reinterpret_cast<const ull*>(p);
}

__global__ __launch_bounds__(WARPS_PER_CTA * 32)
void chive_kernel(const float* __restrict__ frnn, const float* __restrict__ phrnn,
                  const float* __restrict__ syl,
                  const float* __restrict__ Wx_f, const float* __restrict__ Wh_f,
                  const float* __restrict__ b_f,
                  const float* __restrict__ Wx_p, const float* __restrict__ Wh_p,
                  const float* __restrict__ b_p,
                  const float* __restrict__ Wx_s, const float* __restrict__ Wh_s,
                  const float* __restrict__ b_s,
                  const int* __restrict__ fclk, const int* __restrict__ pclk,
                  const int* __restrict__ sfreq,
                  float* __restrict__ out)
{
    // Weights: A-phase (f,p) interleaved pairs; B-phase (Wx_s, Wh_s) interleaved pairs.
    __shared__ __align__(16) float sWA[(DF + HID) * HID * 2];  // 10 KB
    __shared__ __align__(16) float sWS[HID * HID * 2];         // 8 KB
    __shared__ __align__(16) float sBfp[HID * 2];
    __shared__ __align__(16) float sBs[HID];
    __shared__ unsigned char sFlag[T_STEPS];
    // Per-warp broadcast state (16B-stride arrays; conflict-free STS.128)
    __shared__ __align__(16) float sA   [WARPS_PER_CTA][HID * 4]; // (hf0,hp0,hf1,hp1)[j]
    __shared__ __align__(16) float sIn  [WARPS_PER_CTA][DF  * 4]; // (xf0,xp0,xf1,xp1)[j]
    __shared__ __align__(16) float sB01a[WARPS_PER_CTA][HID * 4]; // (hf0,hs0_0,hp0,hs1_0)[j]
    __shared__ __align__(16) float sB01b[WARPS_PER_CTA][HID * 4]; // (hf1,hs0_1,hp1,hs1_1)[j]
    __shared__ __align__(16) float sB2  [WARPS_PER_CTA][HID * 4]; // (xs0,hs2_0,xs1,hs2_1)[j]

    const int tid = threadIdx.x;
    const int nt  = blockDim.x;

    // ---- prologue: stage weights + flags ----
    for (int i = tid; i < DF * HID; i += nt) {
        sWA[2 * i]     = Wx_f[i];
        sWA[2 * i + 1] = Wx_p[i];
    }
    for (int i = tid; i < HID * HID; i += nt) {
        sWA[2 * (DF * HID + i)]     = Wh_f[i];
        sWA[2 * (DF * HID + i) + 1] = Wh_p[i];
        sWS[2 * i]     = Wx_s[i];
        sWS[2 * i + 1] = Wh_s[i];
    }
    for (int i = tid; i < HID; i += nt) {
        sBfp[2 * i]     = b_f[i];
        sBfp[2 * i + 1] = b_p[i];
        sBs[i]          = b_s[i];
    }
    for (int t = tid; t < T_STEPS; t += nt) {
        unsigned f = 0u;
        if ((t % (fclk[t] + 1)) == 0) f |= 1u;
        if ((t % (pclk[t] + 1)) == 0) f |= 2u;
        if (sfreq[t] == 1)            f |= 4u;
        sFlag[t] = (unsigned char)f;
    }

    const int w    = tid >> 5;
    const int lane = tid & 31;
    const int b0   = (blockIdx.x * WARPS_PER_CTA + w) * ELEMS_PER_WARP;

    float* A_   = sA[w];
    float* In_  = sIn[w];
    float* B0a_ = sB01a[w];
    float* B0b_ = sB01b[w];
    float* B2_  = sB2[w];

    // init A-broadcast state to zeros
    *(float4*)&A_[lane * 4] = make_float4(0.f, 0.f, 0.f, 0.f);
    __syncthreads();

    // ---- loader roles: lanes 0-7 cover frnn/phrnn (float4 each), 8-19 cover syl ----
    int e = 0, chunk = 0;
    const float* baseP = 0;
    int strideT = 0;
    const bool loader = lane < 20;
    if (lane < 8) {
        e = (lane >> 1) & 1;
        chunk = lane & 1;
        baseP = ((lane < 4) ? frnn : phrnn) + (b0 + e) * DF + chunk * 4;
        strideT = BATCH * DF;
    } else if (lane < 20) {
        int r = lane - 8;
        e = r / 6;
        chunk = r - 6 * e;
        baseP = syl + (b0 + e) * DS + chunk * 4;
        strideT = BATCH * DS;
    }
    const int compA = e * 2 + ((lane >= 4 && lane < 8) ? 1 : 0); // slot in sIn word
    const int compS = e * 2;                                     // slot in sB2 word
    const int jb    = chunk * 4;

    // register-resident state (neuron index = lane)
    float hf0 = 0.f, hp0 = 0.f, hs0_0 = 0.f, hs1_0 = 0.f, hs2_0 = 0.f;
    float hf1 = 0.f, hp1 = 0.f, hs0_1 = 0.f, hs1_1 = 0.f, hs2_1 = 0.f;

    const ull   biasfp = lds2(&sBfp[2 * lane]);
    const float bsl    = sBs[lane];

    float4 cur = loader ? *(const float4*)baseP : make_float4(0.f, 0.f, 0.f, 0.f);

    for (int t = 0; t < T_STEPS; t++) {
        float4 nxt = make_float4(0.f, 0.f, 0.f, 0.f);
        if (loader && t + 1 < T_STEPS)
            nxt = *(const float4*)(baseP + (size_t)(t + 1) * strideT);

        const unsigned fl = sFlag[t];

        // ---------------- phase A: f & p cells, 2 elements ----------------
        if (fl & 3u) {
            if (lane < 8) {
                In_[(jb + 0) * 4 + compA] = cur.x;
                In_[(jb + 1) * 4 + compA] = cur.y;
                In_[(jb + 2) * 4 + compA] = cur.z;
                In_[(jb + 3) * 4 + compA] = cur.w;
            }
            __syncwarp();
            ull a0A = biasfp, a0B = 0ull, a1A = biasfp, a1B = 0ull;
            #pragma unroll
            for (int j = 0; j < DF; j++) {
                ull wv = lds2(&sWA[(j * HID + lane) * 2]);
                ulonglong2 x = *(const ulonglong2*)&In_[j * 4]; // .x=(xf0,xp0) .y=(xf1,xp1)
                if (j & 1) { a0B = f2_fma(x.x, wv, a0B); a1B = f2_fma(x.y, wv, a1B); }
                else       { a0A = f2_fma(x.x, wv, a0A); a1A = f2_fma(x.y, wv, a1A); }
            }
            #pragma unroll
            for (int j = 0; j < HID; j++) {
                ull wv = lds2(&sWA[((DF + j) * HID + lane) * 2]);
                ulonglong2 h = *(const ulonglong2*)&A_[j * 4]; // .x=(hf0,hp0) .y=(hf1,hp1)
                if (j & 1) { a0B = f2_fma(h.x, wv, a0B); a1B = f2_fma(h.y, wv, a1B); }
                else       { a0A = f2_fma(h.x, wv, a0A); a1A = f2_fma(h.y, wv, a1A); }
            }
            float af0, ap0, af1, ap1;
            f2_unpack(f2_add(a0A, a0B), af0, ap0);
            f2_unpack(f2_add(a1A, a1B), af1, ap1);
            if (fl & 1u) { hf0 = fast_tanh(af0); hf1 = fast_tanh(af1); }
            if (fl & 2u) { hp0 = fast_tanh(ap0); hp1 = fast_tanh(ap1); }
            __syncwarp();  // all lanes done reading old sA
            *(float4*)&A_[lane * 4] = make_float4(hf0, hp0, hf1, hp1);
        }

        // ---------------- phase B: syl cell — ONE weight pair serves 3 rows × 2 elems --
        if (fl & 4u) {
            __syncwarp();  // all lanes past previous B reads
            *(float4*)&B0a_[lane * 4] = make_float4(hf0, hs0_0, hp0, hs1_0);
            *(float4*)&B0b_[lane * 4] = make_float4(hf1, hs0_1, hp1, hs1_1);
            B2_[lane * 4 + 1] = hs2_0;
            B2_[lane * 4 + 3] = hs2_1;
            if (lane >= 8 && lane < 20) {
                B2_[(jb + 0) * 4 + compS] = cur.x;
                B2_[(jb + 1) * 4 + compS] = cur.y;
                B2_[(jb + 2) * 4 + compS] = cur.z;
                B2_[(jb + 3) * 4 + compS] = cur.w;
            }
            __syncwarp();
            // accumulators: (x-stack part, Wh part) per row per element
            ull r00 = f2_pack(bsl, 0.f);
            ull r10 = r00, r20 = r00, r01 = r00, r11 = r00, r21 = r00;
            #pragma unroll
            for (int j = 0; j < HID; j++) {
                ull wv = lds2(&sWS[(j * HID + lane) * 2]);       // (Wx_s, Wh_s)
                ulonglong2 q0 = *(const ulonglong2*)&B0a_[j * 4]; // (hf0,hs0_0)(hp0,hs1_0)
                ulonglong2 q1 = *(const ulonglong2*)&B0b_[j * 4];
                ulonglong2 q2 = *(const ulonglong2*)&B2_[j * 4];  // (xs0,hs2_0)(xs1,hs2_1)
                r00 = f2_fma(q0.x, wv, r00);
                r10 = f2_fma(q0.y, wv, r10);
                r01 = f2_fma(q1.x, wv, r01);
                r11 = f2_fma(q1.y, wv, r11);
                r20 = f2_fma(q2.x, wv, r20);
                r21 = f2_fma(q2.y, wv, r21);
            }
            float xa, ha;
            f2_unpack(r00, xa, ha); hs0_0 = fast_tanh(xa + ha);
            f2_unpack(r10, xa, ha); hs1_0 = fast_tanh(xa + ha);
            f2_unpack(r20, xa, ha); hs2_0 = fast_tanh(xa + ha);
            f2_unpack(r01, xa, ha); hs0_1 = fast_tanh(xa + ha);
            f2_unpack(r11, xa, ha); hs1_1 = fast_tanh(xa + ha);
            f2_unpack(r21, xa, ha); hs2_1 = fast_tanh(xa + ha);
        }

        cur = nxt;
    }

    // output h_s: [3, B, H]
    out[(0 * BATCH + b0    ) * HID + lane] = hs0_0;
    out[(1 * BATCH + b0    ) * HID + lane] = hs1_0;
    out[(2 * BATCH + b0    ) * HID + lane] = hs2_0;
    out[(0 * BATCH + b0 + 1) * HID + lane] = hs0_1;
    out[(1 * BATCH + b0 + 1) * HID + lane] = hs1_1;
    out[(2 * BATCH + b0 + 1) * HID + lane] = hs2_1;
}

extern "C" void kernel_launch(void* const* d_in, const int* in_sizes, int n_in,
                              void* d_out, int out_size) {
    const float* frnn  = (const float*)d_in[0];
    const float* phrnn = (const float*)d_in[1];
    const float* syl   = (const float*)d_in[2];
    const float* Wx_f  = (const float*)d_in[3];
    const float* Wh_f  = (const float*)d_in[4];
    const float* b_f   = (const float*)d_in[5];
    const float* Wx_p  = (const float*)d_in[6];
    const float* Wh_p  = (const float*)d_in[7];
    const float* b_p   = (const float*)d_in[8];
    const float* Wx_s  = (const float*)d_in[9];
    const float* Wh_s  = (const float*)d_in[10];
    const float* b_s   = (const float*)d_in[11];
    const int*   fclk  = (const int*)d_in[12];
    const int*   pclk  = (const int*)d_in[13];
    const int*   sfreq = (const int*)d_in[14];
    float* out = (float*)d_out;

    dim3 grid(BATCH / (WARPS_PER_CTA * ELEMS_PER_WARP));
    dim3 block(WARPS_PER_CTA * 32);
    chive_kernel<<<grid, block>>>(frnn, phrnn, syl,
                                  Wx_f, Wh_f, b_f,
                                  Wx_p, Wh_p, b_p,
                                  Wx_s, Wh_s, b_s,
                                  fclk, pclk, sfreq, out);
}